// round 9
// baseline (speedup 1.0000x reference)
#include <cuda_runtime.h>
#include <cuda_fp16.h>
#include <cstdint>

#define N_NODES 100000
#define N_EDGES 300000
#define IN_CH   256
#define NCOLS   512

// Scratch (__device__ globals; no allocs allowed)
__device__ __half   g_C[(size_t)N_NODES * NCOLS];    // scaled layer-1 pre-act, fp16 (102.4 MB)
__device__ __half   g_Bt[NCOLS * IN_CH];             // fp16 rearranged W1 scaled by |W2[h]|
__device__ float    g_b1s[IN_CH];                    // |W2[h]| * b1[h]
__device__ uint32_t g_sgn[8];                        // signbit(W2[h]) bitmask

__device__ __forceinline__ uint32_t smem_u32(const void* p) {
    uint32_t a;
    asm("{ .reg .u64 t; cvta.to.shared.u64 t, %1; cvt.u32.u64 %0, t; }" : "=r"(a) : "l"(p));
    return a;
}

// ---------------------------------------------------------------------------
// Prep B: g_Bt[n][k] = fp16( (n<256 ? W1[n][k] : W1[n-256][256+k]) * |W2[n&255]| )
// Also: g_b1s[h] = |W2[h]|*b1[h];  g_sgn sign bitmask of W2.
// ---------------------------------------------------------------------------
__global__ void prep_b_kernel(const float* __restrict__ W1,
                              const float* __restrict__ W2,
                              const float* __restrict__ b1) {
    int idx = blockIdx.x * blockDim.x + threadIdx.x;
    if (idx < NCOLS * IN_CH) {
        int n = idx >> 8;
        int k = idx & 255;
        int h = n & 255;
        float w = W1[h * 512 + (n >> 8) * 256 + k] * fabsf(W2[h]);
        g_Bt[idx] = __float2half(w);
    }
    if (idx < IN_CH) g_b1s[idx] = fabsf(W2[idx]) * b1[idx];
    if (idx < 8) {
        uint32_t m = 0;
        for (int j = 0; j < 32; j++)
            m |= (__float_as_uint(W2[idx * 32 + j]) >> 31) << j;
        g_sgn[idx] = m;
    }
}

// ---------------------------------------------------------------------------
// PERSISTENT fp16 mma.sync GEMM, cp.async 3-stage ring across all tiles.
// A loaded as RAW fp32 z (converted to fp16 at fragment-load time — same
// __floats2half2_rn rounding as the old prep_z), B as fp16 from g_Bt.
// g_C[M,512] = fp16( fp16(z[M,256]) @ g_Bt[512,256]^T ) (+ bias on dst half)
// CTA tile 128x256, BK=64 halves, 256 threads = 8 warps (2x4), warp 64x64.
// ---------------------------------------------------------------------------
#define BM 128
#define BN 256
#define BKH 64                      // K halves per chunk
#define LDW 36                      // B row stride in u32 words (32 + 4 pad)
#define LDA 68                      // A fp32 row stride in floats (64 + 4 pad)
#define KTILES (IN_CH / BKH)        // 4 chunks per tile
#define A_W (BM * LDA)              // 8704 words (fp32)
#define B_W (BN * LDW)              // 9216 words
#define NSTAGE 3
#define NGRID 148
#define MTILES 782                  // ceil(100000/128)
#define NTILES (MTILES * 2)         // 1564
#define SMEM_BYTES ((NSTAGE * (A_W + B_W)) * 4)   // 215040

#define CP_ASYNC(dst, src, sz) \
    asm volatile("cp.async.ca.shared.global [%0], [%1], 16, %2;" \
                 :: "r"(dst), "l"(src), "r"(sz))
#define CP_COMMIT()  asm volatile("cp.async.commit_group;" ::: "memory")
#define CP_WAIT2()   asm volatile("cp.async.wait_group 2;" ::: "memory")

__global__ __launch_bounds__(256, 1) void gemm_persist_kernel(const float* __restrict__ z) {
    extern __shared__ uint32_t smw[];
    const uint32_t sb = smem_u32(smw);

    const int tid  = threadIdx.x;
    const int wid  = tid >> 5;
    const int lane = tid & 31;
    const int g = lane >> 2;            // 0..7
    const int t = lane & 3;             // 0..3
    const int wm = (wid & 1) * 64;
    const int wn = (wid >> 1) * 64;
    const int bid = blockIdx.x;

    // local chunk count: 4 per tile, tiles bid, bid+148, ...
    const int ntile_local = (NTILES - 1 - bid) / NGRID + 1;
    const int L = ntile_local * 4;

    float c[4][8][4];
    #pragma unroll
    for (int i = 0; i < 4; i++)
        #pragma unroll
        for (int j = 0; j < 8; j++)
            #pragma unroll
            for (int r = 0; r < 4; r++)
                c[i][j][r] = 0.f;

    // Issue chunk lq into ring stage (lq % 3).
    auto issue = [&](int lq) {
        const int tile = bid + (lq >> 2) * NGRID;
        const int kt   = lq & 3;
        const int m0   = (tile >> 1) * BM;
        const int n0   = (tile & 1) << 8;
        const int buf  = lq % NSTAGE;
        const uint32_t abase = sb + (uint32_t)(buf * A_W) * 4;
        const uint32_t bbase = sb + (uint32_t)(NSTAGE * A_W + buf * B_W) * 4;
        // A: 128 rows x 64 fp32 = 2048 16B chunks / 256 thr = 8 each
        #pragma unroll
        for (int i = 0; i < 8; i++) {
            int idx = tid + i * 256;        // 0..2047
            int row = idx >> 4;             // 0..127
            int c4  = idx & 15;             // 16B chunk (4 floats)
            int grow = m0 + row;
            const float* src = z + (size_t)grow * IN_CH + kt * BKH + c4 * 4;
            uint32_t dst = abase + (uint32_t)(row * LDA + c4 * 4) * 4;
            int sz = (grow < N_NODES) ? 16 : 0;
            CP_ASYNC(dst, src, sz);
        }
        // B: 256 rows x 64 halves = 2048 16B chunks / 256 thr = 8 each
        #pragma unroll
        for (int i = 0; i < 8; i++) {
            int idx = tid + i * 256;
            int row = idx >> 3;             // 0..255
            int c16 = idx & 7;
            const __half* src = g_Bt + (size_t)(n0 + row) * IN_CH + kt * BKH + c16 * 8;
            uint32_t dst = bbase + (uint32_t)(row * LDW + c16 * 4) * 4;
            CP_ASYNC(dst, src, 16);
        }
    };

    issue(0); CP_COMMIT();
    issue(1); CP_COMMIT();
    issue(2); CP_COMMIT();

    for (int lq = 0; lq < L; lq++) {
        const int tile = bid + (lq >> 2) * NGRID;
        const int kt   = lq & 3;
        const int buf  = lq % NSTAGE;
        CP_WAIT2();
        __syncthreads();

        const float*    As = (const float*)(smw + buf * A_W);
        const uint32_t* Bs = smw + NSTAGE * A_W + buf * B_W;

        #pragma unroll
        for (int s = 0; s < 4; s++) {       // 4 k16 steps per chunk
            const int kb  = s * 8;          // B word offset
            const int kbf = s * 16;         // A float offset
            uint32_t bfr[8][2];
            #pragma unroll
            for (int nf = 0; nf < 8; nf++) {
                const int br = wn + nf * 8 + g;
                bfr[nf][0] = Bs[br * LDW + kb + t];
                bfr[nf][1] = Bs[br * LDW + kb + t + 4];
            }
            #pragma unroll
            for (int mf = 0; mf < 4; mf++) {
                const int ar = wm + mf * 16 + g;
                float2 p0 = *(const float2*)&As[ar * LDA + kbf + 2 * t];
                float2 p1 = *(const float2*)&As[(ar + 8) * LDA + kbf + 2 * t];
                float2 p2 = *(const float2*)&As[ar * LDA + kbf + 2 * t + 8];
                float2 p3 = *(const float2*)&As[(ar + 8) * LDA + kbf + 2 * t + 8];
                union { __half2 h; uint32_t u; } a0, a1, a2, a3;
                a0.h = __floats2half2_rn(p0.x, p0.y);
                a1.h = __floats2half2_rn(p1.x, p1.y);
                a2.h = __floats2half2_rn(p2.x, p2.y);
                a3.h = __floats2half2_rn(p3.x, p3.y);
                #pragma unroll
                for (int nf = 0; nf < 8; nf++) {
                    asm volatile(
                        "mma.sync.aligned.m16n8k16.row.col.f32.f16.f16.f32 "
                        "{%0,%1,%2,%3}, {%4,%5,%6,%7}, {%8,%9}, {%0,%1,%2,%3};"
                        : "+f"(c[mf][nf][0]), "+f"(c[mf][nf][1]),
                          "+f"(c[mf][nf][2]), "+f"(c[mf][nf][3])
                        : "r"(a0.u), "r"(a1.u), "r"(a2.u), "r"(a3.u),
                          "r"(bfr[nf][0]), "r"(bfr[nf][1]));
                }
            }
        }

        // Tile finished: epilogue (overlaps with in-flight cp.async of next tile)
        if (kt == 3) {
            const int m0 = (tile >> 1) * BM;
            const int n0 = (tile & 1) << 8;
            const bool dsthalf = (n0 != 0);
            #pragma unroll
            for (int mf = 0; mf < 4; mf++) {
                const int row_a = m0 + wm + mf * 16 + g;
                const int row_b = row_a + 8;
                #pragma unroll
                for (int nf = 0; nf < 8; nf++) {
                    const int colh = wn + nf * 8 + t * 2;
                    float bx = 0.f, by = 0.f;
                    if (dsthalf) { bx = g_b1s[colh]; by = g_b1s[colh + 1]; }
                    const int col = n0 + colh;
                    if (row_a < N_NODES)
                        *(__half2*)&g_C[(size_t)row_a * NCOLS + col] =
                            __floats2half2_rn(c[mf][nf][0] + bx, c[mf][nf][1] + by);
                    if (row_b < N_NODES)
                        *(__half2*)&g_C[(size_t)row_b * NCOLS + col] =
                            __floats2half2_rn(c[mf][nf][2] + bx, c[mf][nf][3] + by);
                }
            }
            #pragma unroll
            for (int i = 0; i < 4; i++)
                #pragma unroll
                for (int j = 0; j < 8; j++)
                    #pragma unroll
                    for (int r = 0; r < 4; r++)
                        c[i][j][r] = 0.f;
        }

        __syncthreads();
        if (lq + NSTAGE < L) issue(lq + NSTAGE);
        CP_COMMIT();
    }
}

// ---------------------------------------------------------------------------
// Edge kernel: TWO edges per warp (16 lanes each, 16 channels per lane).
// out[e] = b2 + sum_h sign(W2[h]) * relu(Cs[src][h] + Cd[dst][h])
// ---------------------------------------------------------------------------
__global__ __launch_bounds__(256) void edge_kernel(
    const int* __restrict__ ei,
    const float* __restrict__ b2,
    float* __restrict__ out)
{
    int warp = (blockIdx.x * blockDim.x + threadIdx.x) >> 5;
    int lane = threadIdx.x & 31;
    int half = lane >> 4;
    int sl   = lane & 15;

    int e = warp * 2 + half;
    if (e >= N_EDGES) return;

    int s = ei[e];
    int d = ei[N_EDGES + e];

    const __half* arow = &g_C[(size_t)s * NCOLS] + sl * 16;
    const __half* brow = &g_C[(size_t)d * NCOLS + IN_CH] + sl * 16;

    union { uint4 u; __half2 h[4]; } ua0, ua1, ub0, ub1;
    ua0.u = *(const uint4*)(arow);
    ua1.u = *(const uint4*)(arow + 8);
    ub0.u = *(const uint4*)(brow);
    ub1.u = *(const uint4*)(brow + 8);

    uint32_t m16 = (g_sgn[sl >> 1] >> ((sl & 1) * 16)) & 0xFFFFu;

    float sum = 0.f;
    #pragma unroll
    for (int i = 0; i < 4; i++) {
        float2 av = __half22float2(ua0.h[i]);
        float2 bv = __half22float2(ub0.h[i]);
        float r0 = fmaxf(av.x + bv.x, 0.f);
        float r1 = fmaxf(av.y + bv.y, 0.f);
        sum += __uint_as_float(__float_as_uint(r0) ^ (((m16 >> (2 * i)) & 1u) << 31));
        sum += __uint_as_float(__float_as_uint(r1) ^ (((m16 >> (2 * i + 1)) & 1u) << 31));
    }
    #pragma unroll
    for (int i = 0; i < 4; i++) {
        float2 av = __half22float2(ua1.h[i]);
        float2 bv = __half22float2(ub1.h[i]);
        float r0 = fmaxf(av.x + bv.x, 0.f);
        float r1 = fmaxf(av.y + bv.y, 0.f);
        sum += __uint_as_float(__float_as_uint(r0) ^ (((m16 >> (8 + 2 * i)) & 1u) << 31));
        sum += __uint_as_float(__float_as_uint(r1) ^ (((m16 >> (8 + 2 * i + 1)) & 1u) << 31));
    }

    #pragma unroll
    for (int o = 8; o; o >>= 1)
        sum += __shfl_xor_sync(0xFFFFFFFFu, sum, o);

    if (sl == 0)
        out[e] = sum + b2[0];
}

// ---------------------------------------------------------------------------
extern "C" void kernel_launch(void* const* d_in, const int* in_sizes, int n_in,
                              void* d_out, int out_size)
{
    const float* z   = (const float*)d_in[0];
    const float* W1  = (const float*)d_in[1];
    const float* b1  = (const float*)d_in[2];
    const float* W2  = (const float*)d_in[3];
    const float* b2  = (const float*)d_in[4];
    const int*   ei  = (const int*)d_in[5];
    float*       out = (float*)d_out;

    cudaFuncSetAttribute(gemm_persist_kernel,
                         cudaFuncAttributeMaxDynamicSharedMemorySize, SMEM_BYTES);

    prep_b_kernel<<<(NCOLS * IN_CH + 255) / 256, 256>>>(W1, W2, b1);

    gemm_persist_kernel<<<NGRID, 256, SMEM_BYTES>>>(z);

    int edge_blocks = (N_EDGES / 2 + 7) / 8;   // 8 warps/block, 2 edges/warp
    edge_kernel<<<edge_blocks, 256>>>(ei, b2, out);
}

// round 10
// speedup vs baseline: 1.1608x; 1.1608x over previous
#include <cuda_runtime.h>
#include <cuda_fp16.h>
#include <cstdint>

#define N_NODES 100000
#define N_EDGES 300000
#define IN_CH   256
#define NCOLS   512

// Scratch (__device__ globals; no allocs allowed)
__device__ __half   g_C[(size_t)N_NODES * NCOLS];    // scaled layer-1 pre-act, fp16 (102.4 MB)
__device__ __half   g_Ah[(size_t)N_NODES * IN_CH];   // fp16 z (51.2 MB)
__device__ __half   g_Bt[NCOLS * IN_CH];             // fp16 rearranged W1 scaled by |W2[h]|
__device__ float    g_b1s[IN_CH];                    // |W2[h]| * b1[h]
__device__ uint32_t g_sgn[8];                        // signbit(W2[h]) bitmask

__device__ __forceinline__ uint32_t smem_u32(const void* p) {
    uint32_t a;
    asm("{ .reg .u64 t; cvta.to.shared.u64 t, %1; cvt.u32.u64 %0, t; }" : "=r"(a) : "l"(p));
    return a;
}

// ---------------------------------------------------------------------------
// Prep B: g_Bt[n][k] = fp16( (n<256 ? W1[n][k] : W1[n-256][256+k]) * |W2[n&255]| )
// Also: g_b1s[h] = |W2[h]|*b1[h];  g_sgn sign bitmask of W2.
// ---------------------------------------------------------------------------
__global__ void prep_b_kernel(const float* __restrict__ W1,
                              const float* __restrict__ W2,
                              const float* __restrict__ b1) {
    int idx = blockIdx.x * blockDim.x + threadIdx.x;
    if (idx < NCOLS * IN_CH) {
        int n = idx >> 8;
        int k = idx & 255;
        int h = n & 255;
        float w = W1[h * 512 + (n >> 8) * 256 + k] * fabsf(W2[h]);
        g_Bt[idx] = __float2half(w);
    }
    if (idx < IN_CH) g_b1s[idx] = fabsf(W2[idx]) * b1[idx];
    if (idx < 8) {
        uint32_t m = 0;
        for (int j = 0; j < 32; j++)
            m |= (__float_as_uint(W2[idx * 32 + j]) >> 31) << j;
        g_sgn[idx] = m;
    }
}

// ---------------------------------------------------------------------------
// Prep A: g_Ah = fp16(z), 8 floats per thread
// ---------------------------------------------------------------------------
__global__ __launch_bounds__(256) void prep_z_kernel(const float* __restrict__ z) {
    int idx = blockIdx.x * blockDim.x + threadIdx.x;
    if (idx >= (N_NODES * IN_CH) / 8) return;
    const float4* zp = (const float4*)z;
    float4 v0 = zp[idx * 2], v1 = zp[idx * 2 + 1];
    union { uint4 u; __half2 h[4]; } o;
    o.h[0] = __floats2half2_rn(v0.x, v0.y);
    o.h[1] = __floats2half2_rn(v0.z, v0.w);
    o.h[2] = __floats2half2_rn(v1.x, v1.y);
    o.h[3] = __floats2half2_rn(v1.z, v1.w);
    ((uint4*)g_Ah)[idx] = o.u;
}

// ---------------------------------------------------------------------------
// PERSISTENT fp16 mma.sync GEMM: R8's exact mainloop (fp16 A, ldmatrix) in a
// cross-tile 3-stage cp.async chunk ring (no wave transitions / refills).
// g_C[M,512] = fp16( g_Ah[M,256] @ g_Bt[512,256]^T ) (+ bias on dst half)
// CTA tile 128x256, BKH=64 halves, 256 threads = 8 warps (2x4), warp 64x64.
// ---------------------------------------------------------------------------
#define BM 128
#define BN 256
#define BKH 64                      // K halves per chunk (= 32 u32 words)
#define LDW 36                      // row stride in u32 words (32 + 4 pad)
#define A_W (BM * LDW)              // 4608 words
#define B_W (BN * LDW)              // 9216 words
#define STAGE_W (A_W + B_W)         // 13824 words = 55296 B
#define NSTAGE 3
#define NGRID 148
#define MTILES 782                  // ceil(100000/128)
#define NTILES (MTILES * 2)         // 1564
#define SMEM_BYTES (NSTAGE * STAGE_W * 4)   // 165888

#define CP_ASYNC(dst, src, sz) \
    asm volatile("cp.async.ca.shared.global [%0], [%1], 16, %2;" \
                 :: "r"(dst), "l"(src), "r"(sz))
#define CP_COMMIT()  asm volatile("cp.async.commit_group;" ::: "memory")
#define CP_WAIT2()   asm volatile("cp.async.wait_group 2;" ::: "memory")

__global__ __launch_bounds__(256, 1) void gemm_persist_kernel() {
    extern __shared__ uint32_t smw[];
    const uint32_t sb = smem_u32(smw);

    const int tid  = threadIdx.x;
    const int wid  = tid >> 5;
    const int lane = tid & 31;
    const int g = lane >> 2;            // 0..7
    const int t = lane & 3;             // 0..3
    const int wm = (wid & 1) * 64;
    const int wn = (wid >> 1) * 64;
    const int bid = blockIdx.x;

    // ldmatrix.x4 lane word offset within A tile (R8 layout)
    const uint32_t a_lm_word = (uint32_t)((wm + (lane & 15)) * LDW + (lane >> 4) * 4);

    const int ntile_local = (NTILES - 1 - bid) / NGRID + 1;
    const int L = ntile_local * 4;      // chunks (4 per tile)

    float c[4][8][4];
    #pragma unroll
    for (int i = 0; i < 4; i++)
        #pragma unroll
        for (int j = 0; j < 8; j++)
            #pragma unroll
            for (int r = 0; r < 4; r++)
                c[i][j][r] = 0.f;

    auto issue = [&](int lq) {
        const int tile = bid + (lq >> 2) * NGRID;
        const int kt   = lq & 3;
        const int m0   = (tile >> 1) * BM;
        const int n0   = (tile & 1) << 8;
        const int buf  = lq % NSTAGE;
        const uint32_t abase = sb + (uint32_t)(buf * STAGE_W) * 4;
        const uint32_t bbase = abase + A_W * 4;
        #pragma unroll
        for (int i = 0; i < 4; i++) {
            int idx = tid + i * 256;        // 0..1023
            int row = idx >> 3;             // 0..127
            int c16 = idx & 7;              // 16B chunk along K (8 halves)
            int grow = m0 + row;
            const __half* src = g_Ah + (size_t)grow * IN_CH + kt * BKH + c16 * 8;
            uint32_t dst = abase + (uint32_t)(row * LDW + c16 * 4) * 4;
            int sz = (grow < N_NODES) ? 16 : 0;
            CP_ASYNC(dst, src, sz);
        }
        #pragma unroll
        for (int i = 0; i < 8; i++) {
            int idx = tid + i * 256;        // 0..2047
            int row = idx >> 3;             // 0..255
            int c16 = idx & 7;
            const __half* src = g_Bt + (size_t)(n0 + row) * IN_CH + kt * BKH + c16 * 8;
            uint32_t dst = bbase + (uint32_t)(row * LDW + c16 * 4) * 4;
            CP_ASYNC(dst, src, 16);
        }
    };

    issue(0); CP_COMMIT();
    issue(1); CP_COMMIT();
    issue(2); CP_COMMIT();

    for (int lq = 0; lq < L; lq++) {
        const int tile = bid + (lq >> 2) * NGRID;
        const int kt   = lq & 3;
        const int buf  = lq % NSTAGE;
        CP_WAIT2();
        __syncthreads();

        const uint32_t abase = sb + (uint32_t)(buf * STAGE_W) * 4;
        const uint32_t* Bs = smw + buf * STAGE_W + A_W;
        const uint32_t a_lm_base = abase + a_lm_word * 4;

        #pragma unroll
        for (int s = 0; s < 4; s++) {       // 4 k16 steps per chunk
            const int kb = s * 8;           // word offset
            uint32_t bfr[8][2];
            #pragma unroll
            for (int nf = 0; nf < 8; nf++) {
                const int br = wn + nf * 8 + g;
                bfr[nf][0] = Bs[br * LDW + kb + t];
                bfr[nf][1] = Bs[br * LDW + kb + t + 4];
            }
            #pragma unroll
            for (int mf = 0; mf < 4; mf++) {
                uint32_t a0, a1, a2, a3;
                uint32_t aaddr = a_lm_base + (uint32_t)(mf * 16 * LDW + kb) * 4;
                asm volatile(
                    "ldmatrix.sync.aligned.m8n8.x4.shared.b16 {%0,%1,%2,%3}, [%4];"
                    : "=r"(a0), "=r"(a1), "=r"(a2), "=r"(a3) : "r"(aaddr));
                #pragma unroll
                for (int nf = 0; nf < 8; nf++) {
                    asm volatile(
                        "mma.sync.aligned.m16n8k16.row.col.f32.f16.f16.f32 "
                        "{%0,%1,%2,%3}, {%4,%5,%6,%7}, {%8,%9}, {%0,%1,%2,%3};"
                        : "+f"(c[mf][nf][0]), "+f"(c[mf][nf][1]),
                          "+f"(c[mf][nf][2]), "+f"(c[mf][nf][3])
                        : "r"(a0), "r"(a1), "r"(a2), "r"(a3),
                          "r"(bfr[nf][0]), "r"(bfr[nf][1]));
                }
            }
        }

        // Tile done: epilogue overlaps with the 2 chunks still in flight
        if (kt == 3) {
            const int m0 = (tile >> 1) * BM;
            const int n0 = (tile & 1) << 8;
            const bool dsthalf = (n0 != 0);
            #pragma unroll
            for (int mf = 0; mf < 4; mf++) {
                const int row_a = m0 + wm + mf * 16 + g;
                const int row_b = row_a + 8;
                #pragma unroll
                for (int nf = 0; nf < 8; nf++) {
                    const int colh = wn + nf * 8 + t * 2;
                    float bx = 0.f, by = 0.f;
                    if (dsthalf) { bx = g_b1s[colh]; by = g_b1s[colh + 1]; }
                    const int col = n0 + colh;
                    if (row_a < N_NODES)
                        *(__half2*)&g_C[(size_t)row_a * NCOLS + col] =
                            __floats2half2_rn(c[mf][nf][0] + bx, c[mf][nf][1] + by);
                    if (row_b < N_NODES)
                        *(__half2*)&g_C[(size_t)row_b * NCOLS + col] =
                            __floats2half2_rn(c[mf][nf][2] + bx, c[mf][nf][3] + by);
                }
            }
            #pragma unroll
            for (int i = 0; i < 4; i++)
                #pragma unroll
                for (int j = 0; j < 8; j++)
                    #pragma unroll
                    for (int r = 0; r < 4; r++)
                        c[i][j][r] = 0.f;
        }

        __syncthreads();
        if (lq + NSTAGE < L) issue(lq + NSTAGE);
        CP_COMMIT();
    }
}

// ---------------------------------------------------------------------------
// Edge kernel: FOUR edges per warp (8 lanes each, 32 channels per lane).
// out[e] = b2 + sum_h sign(W2[h]) * relu(Cs[src][h] + Cd[dst][h])
// ---------------------------------------------------------------------------
__global__ __launch_bounds__(256) void edge_kernel(
    const int* __restrict__ ei,
    const float* __restrict__ b2,
    float* __restrict__ out)
{
    int warp = (blockIdx.x * blockDim.x + threadIdx.x) >> 5;
    int lane = threadIdx.x & 31;
    int sub  = lane >> 3;               // which edge within the warp (0..3)
    int sl   = lane & 7;                // sub-lane within the edge (0..7)

    int e = warp * 4 + sub;
    if (e >= N_EDGES) return;

    int s = ei[e];
    int d = ei[N_EDGES + e];

    // lane handles channels sl*32 .. sl*32+31
    const __half* arow = &g_C[(size_t)s * NCOLS] + sl * 32;
    const __half* brow = &g_C[(size_t)d * NCOLS + IN_CH] + sl * 32;

    uint32_t m32 = g_sgn[sl];

    float sum = 0.f;
    #pragma unroll
    for (int j = 0; j < 4; j++) {
        union { uint4 u; __half2 h[4]; } ua, ub;
        ua.u = *(const uint4*)(arow + j * 8);
        ub.u = *(const uint4*)(brow + j * 8);
        #pragma unroll
        for (int i = 0; i < 4; i++) {
            float2 av = __half22float2(ua.h[i]);
            float2 bv = __half22float2(ub.h[i]);
            float r0 = fmaxf(av.x + bv.x, 0.f);
            float r1 = fmaxf(av.y + bv.y, 0.f);
            int bit0 = j * 8 + 2 * i;
            sum += __uint_as_float(__float_as_uint(r0) ^ (((m32 >> bit0) & 1u) << 31));
            sum += __uint_as_float(__float_as_uint(r1) ^ (((m32 >> (bit0 + 1)) & 1u) << 31));
        }
    }

    // Reduce within each 8-lane group
    #pragma unroll
    for (int o = 4; o; o >>= 1)
        sum += __shfl_xor_sync(0xFFFFFFFFu, sum, o);

    if (sl == 0)
        out[e] = sum + b2[0];
}

// ---------------------------------------------------------------------------
extern "C" void kernel_launch(void* const* d_in, const int* in_sizes, int n_in,
                              void* d_out, int out_size)
{
    const float* z   = (const float*)d_in[0];
    const float* W1  = (const float*)d_in[1];
    const float* b1  = (const float*)d_in[2];
    const float* W2  = (const float*)d_in[3];
    const float* b2  = (const float*)d_in[4];
    const int*   ei  = (const int*)d_in[5];
    float*       out = (float*)d_out;

    cudaFuncSetAttribute(gemm_persist_kernel,
                         cudaFuncAttributeMaxDynamicSharedMemorySize, SMEM_BYTES);

    prep_b_kernel<<<(NCOLS * IN_CH + 255) / 256, 256>>>(W1, W2, b1);
    prep_z_kernel<<<(N_NODES * IN_CH / 8 + 255) / 256, 256>>>(z);

    gemm_persist_kernel<<<NGRID, 256, SMEM_BYTES>>>();

    int edge_blocks = (N_EDGES / 4 + 7) / 8;   // 8 warps/block, 4 edges/warp
    edge_kernel<<<edge_blocks, 256>>>(ei, b2, out);
}

// round 11
// speedup vs baseline: 1.3750x; 1.1846x over previous
#include <cuda_runtime.h>
#include <cuda_fp16.h>
#include <cstdint>

#define N_NODES 100000
#define N_EDGES 300000
#define IN_CH   256
#define NCOLS   512

// Scratch (__device__ globals; no allocs allowed)
__device__ __half   g_C[(size_t)N_NODES * NCOLS];    // scaled layer-1 pre-act, fp16 (102.4 MB)
__device__ __half   g_Bt[NCOLS * IN_CH];             // fp16 rearranged W1 scaled by |W2[h]|
__device__ float    g_b1s[IN_CH];                    // |W2[h]| * b1[h]
__device__ uint32_t g_sgn[8];                        // signbit(W2[h]) bitmask

__device__ __forceinline__ uint32_t smem_u32(const void* p) {
    uint32_t a;
    asm("{ .reg .u64 t; cvta.to.shared.u64 t, %1; cvt.u32.u64 %0, t; }" : "=r"(a) : "l"(p));
    return a;
}

// ---------------------------------------------------------------------------
// Prep B: g_Bt[n][k] = fp16( (n<256 ? W1[n][k] : W1[n-256][256+k]) * |W2[n&255]| )
// Also: g_b1s[h] = |W2[h]|*b1[h];  g_sgn sign bitmask of W2.
// ---------------------------------------------------------------------------
__global__ void prep_b_kernel(const float* __restrict__ W1,
                              const float* __restrict__ W2,
                              const float* __restrict__ b1) {
    int idx = blockIdx.x * blockDim.x + threadIdx.x;
    if (idx < NCOLS * IN_CH) {
        int n = idx >> 8;
        int k = idx & 255;
        int h = n & 255;
        float w = W1[h * 512 + (n >> 8) * 256 + k] * fabsf(W2[h]);
        g_Bt[idx] = __float2half(w);
    }
    if (idx < IN_CH) g_b1s[idx] = fabsf(W2[idx]) * b1[idx];
    if (idx < 8) {
        uint32_t m = 0;
        for (int j = 0; j < 32; j++)
            m |= (__float_as_uint(W2[idx * 32 + j]) >> 31) << j;
        g_sgn[idx] = m;
    }
}

// ---------------------------------------------------------------------------
// fp16 mma.sync GEMM (R8 multi-wave structure) with FUSED producer-side A
// conversion: A is LDG'd as raw fp32 one chunk ahead, converted with
// __floats2half2_rn (identical to old prep_z), STS'd to fp16 SMEM; consumer
// path unchanged (ldmatrix). B: 3-stage cp.async ring from g_Bt.
// g_C[M,512] = fp16( fp16(z[M,256]) @ g_Bt[512,256]^T ) (+ bias on dst half)
// CTA tile 128x256, BKH=64 halves, 256 threads = 8 warps (2x4), warp 64x64.
// ---------------------------------------------------------------------------
#define BM 128
#define BN 256
#define BKH 64                      // K halves per chunk (= 32 u32 words)
#define LDW 36                      // row stride in u32 words (32 + 4 pad)
#define KTILES (IN_CH / BKH)        // 4 chunks
#define A_W (BM * LDW)              // 4608 words (fp16 A tile region)
#define B_W (BN * LDW)              // 9216 words
#define STAGE_W (A_W + B_W)         // 13824 words = 55296 B
#define NSTAGE 3
#define SMEM_BYTES (NSTAGE * STAGE_W * 4)   // 165888

#define CP_ASYNC(dst, src, sz) \
    asm volatile("cp.async.ca.shared.global [%0], [%1], 16, %2;" \
                 :: "r"(dst), "l"(src), "r"(sz))
#define CP_COMMIT()  asm volatile("cp.async.commit_group;" ::: "memory")
#define CP_WAIT2()   asm volatile("cp.async.wait_group 2;" ::: "memory")

__global__ __launch_bounds__(256, 1) void gemm_fused_kernel(const float* __restrict__ z) {
    extern __shared__ uint32_t smw[];
    const uint32_t sb = smem_u32(smw);

    const int tid  = threadIdx.x;
    const int wid  = tid >> 5;
    const int lane = tid & 31;
    const int g = lane >> 2;            // 0..7
    const int t = lane & 3;             // 0..3
    const int wm = (wid & 1) * 64;
    const int wn = (wid >> 1) * 64;

    const int m0 = blockIdx.y * BM;
    const int n0 = blockIdx.x * BN;

    // ldmatrix.x4 lane word offset within A tile (proven R8 layout)
    const uint32_t a_lm_word = (uint32_t)((wm + (lane & 15)) * LDW + (lane >> 4) * 4);

    // Per-thread A staging: 8 float4 per chunk (128 rows x 64 fp32 / 256 thr)
    const int a_row = -1; // (computed per i below)
    float4 a_pre[8];

    float c[4][8][4];
    #pragma unroll
    for (int i = 0; i < 4; i++)
        #pragma unroll
        for (int j = 0; j < 8; j++)
            #pragma unroll
            for (int r = 0; r < 4; r++)
                c[i][j][r] = 0.f;

    // ---- A producer: LDG fp32 chunk kt into a_pre
    auto ldgA = [&](int kt) {
        #pragma unroll
        for (int i = 0; i < 8; i++) {
            int idx = tid + i * 256;        // 0..2047
            int row = idx >> 4;             // 0..127
            int c4  = idx & 15;             // float4 index along K (16 per row)
            int grow = m0 + row;
            a_pre[i] = (grow < N_NODES)
                ? *(const float4*)(z + (size_t)grow * IN_CH + kt * BKH + c4 * 4)
                : make_float4(0.f, 0.f, 0.f, 0.f);
        }
    };
    // ---- A producer: convert + STS a_pre into stage buf's A region
    auto stsA = [&](int buf) {
        const uint32_t abase = sb + (uint32_t)(buf * STAGE_W) * 4;
        #pragma unroll
        for (int i = 0; i < 8; i++) {
            int idx = tid + i * 256;
            int row = idx >> 4;
            int c4  = idx & 15;
            union { __half2 h[2]; uint2 u; } v;
            v.h[0] = __floats2half2_rn(a_pre[i].x, a_pre[i].y);
            v.h[1] = __floats2half2_rn(a_pre[i].z, a_pre[i].w);
            uint32_t dst = abase + (uint32_t)(row * LDW + c4 * 2) * 4;
            asm volatile("st.shared.v2.b32 [%0], {%1, %2};"
                         :: "r"(dst), "r"(v.u.x), "r"(v.u.y) : "memory");
        }
    };
    // ---- B producer: cp.async chunk kt into stage buf's B region
    auto issueB = [&](int buf, int kt) {
        const uint32_t bbase = sb + (uint32_t)(buf * STAGE_W + A_W) * 4;
        #pragma unroll
        for (int i = 0; i < 8; i++) {
            int idx = tid + i * 256;        // 0..2047
            int row = idx >> 3;             // 0..255
            int c16 = idx & 7;
            const __half* src = g_Bt + (size_t)(n0 + row) * IN_CH + kt * BKH + c16 * 8;
            uint32_t dst = bbase + (uint32_t)(row * LDW + c16 * 4) * 4;
            CP_ASYNC(dst, src, 16);
        }
    };

    // Prologue
    ldgA(0);
    issueB(0, 0); CP_COMMIT();
    issueB(1, 1); CP_COMMIT();
    issueB(2, 2); CP_COMMIT();
    stsA(0);                 // stalls on chunk0 LDG (startup only)
    ldgA(1);

    for (int kt = 0; kt < KTILES; kt++) {
        const int buf = kt % NSTAGE;
        CP_WAIT2();
        __syncthreads();

        // Producer-side A for chunk kt+1 (stage free since iteration kt-2)
        if (kt + 1 < KTILES) {
            stsA((kt + 1) % NSTAGE);
            if (kt + 2 < KTILES) ldgA(kt + 2);   // latency covered by MMA loop
        }

        const uint32_t abase = sb + (uint32_t)(buf * STAGE_W) * 4;
        const uint32_t* Bs = smw + buf * STAGE_W + A_W;
        const uint32_t a_lm_base = abase + a_lm_word * 4;

        #pragma unroll
        for (int s = 0; s < 4; s++) {       // 4 k16 steps per chunk
            const int kb = s * 8;           // word offset
            uint32_t bfr[8][2];
            #pragma unroll
            for (int nf = 0; nf < 8; nf++) {
                const int br = wn + nf * 8 + g;
                bfr[nf][0] = Bs[br * LDW + kb + t];
                bfr[nf][1] = Bs[br * LDW + kb + t + 4];
            }
            #pragma unroll
            for (int mf = 0; mf < 4; mf++) {
                uint32_t a0, a1, a2, a3;
                uint32_t aaddr = a_lm_base + (uint32_t)(mf * 16 * LDW + kb) * 4;
                asm volatile(
                    "ldmatrix.sync.aligned.m8n8.x4.shared.b16 {%0,%1,%2,%3}, [%4];"
                    : "=r"(a0), "=r"(a1), "=r"(a2), "=r"(a3) : "r"(aaddr));
                #pragma unroll
                for (int nf = 0; nf < 8; nf++) {
                    asm volatile(
                        "mma.sync.aligned.m16n8k16.row.col.f32.f16.f16.f32 "
                        "{%0,%1,%2,%3}, {%4,%5,%6,%7}, {%8,%9}, {%0,%1,%2,%3};"
                        : "+f"(c[mf][nf][0]), "+f"(c[mf][nf][1]),
                          "+f"(c[mf][nf][2]), "+f"(c[mf][nf][3])
                        : "r"(a0), "r"(a1), "r"(a2), "r"(a3),
                          "r"(bfr[nf][0]), "r"(bfr[nf][1]));
                }
            }
        }
        __syncthreads();
        if (kt + NSTAGE < KTILES) issueB((kt + NSTAGE) % NSTAGE, kt + NSTAGE);
        CP_COMMIT();
    }

    // Epilogue: add scaled bias on dst half, convert to fp16
    const bool dsthalf = (n0 >= 256);
    #pragma unroll
    for (int mf = 0; mf < 4; mf++) {
        const int row_a = m0 + wm + mf * 16 + g;
        const int row_b = row_a + 8;
        #pragma unroll
        for (int nf = 0; nf < 8; nf++) {
            const int colh = wn + nf * 8 + t * 2;
            float bx = 0.f, by = 0.f;
            if (dsthalf) { bx = g_b1s[colh]; by = g_b1s[colh + 1]; }
            const int col = n0 + colh;
            if (row_a < N_NODES)
                *(__half2*)&g_C[(size_t)row_a * NCOLS + col] =
                    __floats2half2_rn(c[mf][nf][0] + bx, c[mf][nf][1] + by);
            if (row_b < N_NODES)
                *(__half2*)&g_C[(size_t)row_b * NCOLS + col] =
                    __floats2half2_rn(c[mf][nf][2] + bx, c[mf][nf][3] + by);
        }
    }
}

// ---------------------------------------------------------------------------
// Edge kernel: TWO edges per warp (16 lanes each, 16 channels per lane) — R8.
// out[e] = b2 + sum_h sign(W2[h]) * relu(Cs[src][h] + Cd[dst][h])
// ---------------------------------------------------------------------------
__global__ __launch_bounds__(256) void edge_kernel(
    const int* __restrict__ ei,
    const float* __restrict__ b2,
    float* __restrict__ out)
{
    int warp = (blockIdx.x * blockDim.x + threadIdx.x) >> 5;
    int lane = threadIdx.x & 31;
    int half = lane >> 4;
    int sl   = lane & 15;

    int e = warp * 2 + half;
    if (e >= N_EDGES) return;

    int s = ei[e];
    int d = ei[N_EDGES + e];

    const __half* arow = &g_C[(size_t)s * NCOLS] + sl * 16;
    const __half* brow = &g_C[(size_t)d * NCOLS + IN_CH] + sl * 16;

    union { uint4 u; __half2 h[4]; } ua0, ua1, ub0, ub1;
    ua0.u = *(const uint4*)(arow);
    ua1.u = *(const uint4*)(arow + 8);
    ub0.u = *(const uint4*)(brow);
    ub1.u = *(const uint4*)(brow + 8);

    uint32_t m16 = (g_sgn[sl >> 1] >> ((sl & 1) * 16)) & 0xFFFFu;

    float sum = 0.f;
    #pragma unroll
    for (int i = 0; i < 4; i++) {
        float2 av = __half22float2(ua0.h[i]);
        float2 bv = __half22float2(ub0.h[i]);
        float r0 = fmaxf(av.x + bv.x, 0.f);
        float r1 = fmaxf(av.y + bv.y, 0.f);
        sum += __uint_as_float(__float_as_uint(r0) ^ (((m16 >> (2 * i)) & 1u) << 31));
        sum += __uint_as_float(__float_as_uint(r1) ^ (((m16 >> (2 * i + 1)) & 1u) << 31));
    }
    #pragma unroll
    for (int i = 0; i < 4; i++) {
        float2 av = __half22float2(ua1.h[i]);
        float2 bv = __half22float2(ub1.h[i]);
        float r0 = fmaxf(av.x + bv.x, 0.f);
        float r1 = fmaxf(av.y + bv.y, 0.f);
        sum += __uint_as_float(__float_as_uint(r0) ^ (((m16 >> (8 + 2 * i)) & 1u) << 31));
        sum += __uint_as_float(__float_as_uint(r1) ^ (((m16 >> (8 + 2 * i + 1)) & 1u) << 31));
    }

    #pragma unroll
    for (int o = 8; o; o >>= 1)
        sum += __shfl_xor_sync(0xFFFFFFFFu, sum, o);

    if (sl == 0)
        out[e] = sum + b2[0];
}

// ---------------------------------------------------------------------------
extern "C" void kernel_launch(void* const* d_in, const int* in_sizes, int n_in,
                              void* d_out, int out_size)
{
    const float* z   = (const float*)d_in[0];
    const float* W1  = (const float*)d_in[1];
    const float* b1  = (const float*)d_in[2];
    const float* W2  = (const float*)d_in[3];
    const float* b2  = (const float*)d_in[4];
    const int*   ei  = (const int*)d_in[5];
    float*       out = (float*)d_out;

    cudaFuncSetAttribute(gemm_fused_kernel,
                         cudaFuncAttributeMaxDynamicSharedMemorySize, SMEM_BYTES);

    prep_b_kernel<<<(NCOLS * IN_CH + 255) / 256, 256>>>(W1, W2, b1);

    dim3 grid(NCOLS / BN, (N_NODES + BM - 1) / BM);   // (2, 782)
    gemm_fused_kernel<<<grid, 256, SMEM_BYTES>>>(z);

    int edge_blocks = (N_EDGES / 2 + 7) / 8;   // 8 warps/block, 2 edges/warp
    edge_kernel<<<edge_blocks, 256>>>(ei, b2, out);
}